// round 9
// baseline (speedup 1.0000x reference)
#include <cuda_runtime.h>
#include <cuda_bf16.h>
#include <float.h>
#include <math.h>

// Problem constants
#define B 64
#define IN_DIM 256
#define H 512
#define M 64
#define N 8192
#define GJ 2048          // 4*H
#define KPART 768        // inp + h K-columns
#define DTILE 128        // rows per Mem tile (64 tiles per batch)
#define GB 16            // batches per pipeline group (4 groups)

// Output layout (floats)
#define OUT_C_OFF (B*H)
#define OUT_R_OFF (2*B*H)
#define OUT_W_OFF (2*B*H + B*N)
#define OUT_M_OFF (2*B*H + 2*B*N)

// Scratch (static device globals — no allocation)
__device__ float g_k[B*M];
__device__ __align__(128) float g_par[B*32];
__device__ float g_logit[B*N];
__device__ float g_mpart[B*64*M];
__device__ float g_gatesT[GJ*B];              // partial gates [j][b]
__device__ float g_ea[B*2*M];

// Flags (zero-init). Set/consume within one launch; reset in a DIFFERENT,
// non-adjacent launch to avoid same-launch races:
//  fA: set+used P1      -> reset P2 (addr blocks)
//  fB: set+used P2..P5  -> reset P7 (addr blocks)
//  fC: set+used P3..P6  -> reset P7 (addr blocks)
//  fD: set+used P4..P7  -> reset P1 (ctrl blocks, next replay)
__device__ int fA[B];
__device__ int fB[B];
__device__ int fC[B];
__device__ int fD[B];

__device__ __forceinline__ float sigf(float x) { return 1.0f / (1.0f + __expf(-x)); }

__device__ __forceinline__ void spin_on(int* f)
{
    if (threadIdx.x == 0) {
        while (atomicAdd(f, 0) == 0) __nanosleep(64);
    }
    __syncthreads();
    __threadfence();
}

__device__ __forceinline__ void release(int* f)
{
    __threadfence();
    __syncthreads();
    if (threadIdx.x == 0) atomicExch(f, 1);
}

// ---------------------------------------------------------------------------
// Block reductions (256 threads, 8 warps)
// ---------------------------------------------------------------------------
__device__ __forceinline__ float bsum(float v, float* red)
{
    #pragma unroll
    for (int o = 16; o; o >>= 1) v += __shfl_xor_sync(0xffffffffu, v, o);
    int t = threadIdx.x;
    if ((t & 31) == 0) red[t >> 5] = v;
    __syncthreads();
    if (t < 8) {
        v = red[t];
        #pragma unroll
        for (int o = 4; o; o >>= 1) v += __shfl_xor_sync(0xffu, v, o);
        if (t == 0) red[0] = v;
    }
    __syncthreads();
    float r = red[0];
    __syncthreads();
    return r;
}

__device__ __forceinline__ float bmax(float v, float* red)
{
    #pragma unroll
    for (int o = 16; o; o >>= 1) v = fmaxf(v, __shfl_xor_sync(0xffffffffu, v, o));
    int t = threadIdx.x;
    if ((t & 31) == 0) red[t >> 5] = v;
    __syncthreads();
    if (t < 8) {
        v = red[t];
        #pragma unroll
        for (int o = 4; o; o >>= 1) v = fmaxf(v, __shfl_xor_sync(0xffu, v, o));
        if (t == 0) red[0] = v;
    }
    __syncthreads();
    float r = red[0];
    __syncthreads();
    return r;
}

// ---------------------------------------------------------------------------
// Controller core: hs (h state) already in shared memory.
// ---------------------------------------------------------------------------
__device__ void controller_core(int b, const float* hs,
                                const float* __restrict__ kw, const float* __restrict__ kb,
                                const float* __restrict__ cw, const float* __restrict__ cb,
                                const float* __restrict__ sw, const float* __restrict__ sb,
                                const float* __restrict__ ww, const float* __restrict__ wb)
{
    int t = threadIdx.x;
    __shared__ float ks[M];
    __shared__ float cvs[3];
    __shared__ float ss[3];

    if (t < M) {
        const float4* w4 = (const float4*)(kw + (size_t)t * H);
        float acc = kb[t];
        #pragma unroll 8
        for (int q = 0; q < H/4; q++) {
            float4 wv = w4[q]; int j = q*4;
            acc += wv.x*hs[j] + wv.y*hs[j+1] + wv.z*hs[j+2] + wv.w*hs[j+3];
        }
        ks[t] = tanhf(acc);
    } else if (t < M + 3) {
        int r = t - M;
        const float4* w4 = (const float4*)(cw + (size_t)r * H);
        float acc = cb[r];
        for (int q = 0; q < H/4; q++) {
            float4 wv = w4[q]; int j = q*4;
            acc += wv.x*hs[j] + wv.y*hs[j+1] + wv.z*hs[j+2] + wv.w*hs[j+3];
        }
        cvs[r] = acc;
    } else if (t < M + 6) {
        int r = t - M - 3;
        const float4* w4 = (const float4*)(sw + (size_t)r * H);
        float acc = sb[r];
        for (int q = 0; q < H/4; q++) {
            float4 wv = w4[q]; int j = q*4;
            acc += wv.x*hs[j] + wv.y*hs[j+1] + wv.z*hs[j+2] + wv.w*hs[j+3];
        }
        ss[r] = acc;
    } else if (ww != nullptr && t >= 70 && t < 70 + 2*M) {
        int r = t - 70;
        const float4* w4 = (const float4*)(ww + (size_t)r * H);
        float acc = wb[r];
        for (int q = 0; q < H/4; q++) {
            float4 wv = w4[q]; int j = q*4;
            acc += wv.x*hs[j] + wv.y*hs[j+1] + wv.z*hs[j+2] + wv.w*hs[j+3];
        }
        g_ea[b*2*M + r] = (r < M) ? sigf(acc) : acc;
    }
    __syncthreads();

    if (t < M) g_k[b*M + t] = ks[t];
    if (t == 0) {
        float mx = fmaxf(ss[0], fmaxf(ss[1], ss[2]));
        float e0 = __expf(ss[0]-mx), e1 = __expf(ss[1]-mx), e2 = __expf(ss[2]-mx);
        float tot = e0 + e1 + e2;
        float nk = 0.0f;
        for (int j = 0; j < M; j++) nk += ks[j]*ks[j];
        g_par[b*32 + 0] = fmaxf(cvs[0], 0.0f) + 0.0001f;
        g_par[b*32 + 1] = sigf(cvs[1]);
        g_par[b*32 + 2] = fmaxf(cvs[2], 0.0f) + 1.0001f;
        g_par[b*32 + 3] = e0/tot;
        g_par[b*32 + 4] = e1/tot;
        g_par[b*32 + 5] = e2/tot;
        g_par[b*32 + 6] = nk;
    }
}

__device__ void controller_load(int b, const float* __restrict__ hstate,
                                const float* kw, const float* kb,
                                const float* cw, const float* cb,
                                const float* sw, const float* sb,
                                const float* ww, const float* wb)
{
    __shared__ float hs[H];
    int t = threadIdx.x;
    for (int i = t; i < H; i += 256) hs[i] = hstate[(size_t)b*H + i];
    __syncthreads();
    controller_core(b, hs, kw, kb, cw, cb, sw, sb, ww, wb);
}

// ---------------------------------------------------------------------------
// GEMM-partial: gatesT[j][b] = bias_j + inp[b]@W_ih[j,:256] + h[b]@W_hh[j,:]
// ---------------------------------------------------------------------------
__device__ void gemm_partial(int gbid,
                             const float* __restrict__ inp,
                             const float* __restrict__ h,
                             const float* __restrict__ W_ih,
                             const float* __restrict__ b_ih,
                             const float* __restrict__ W_hh,
                             const float* __restrict__ b_hh)
{
    __shared__ float Xs[64][33];
    __shared__ float Ws[32][33];
    int t  = threadIdx.x;
    int tx = t & 15;
    int ty = t >> 4;
    int jbase = gbid * 32;
    int lrow = t >> 2;
    int lcol = (t & 3) * 8;
    int wrow = t >> 3;
    int wcol = (t & 7) * 4;

    float acc[4][2];
    #pragma unroll
    for (int i = 0; i < 4; i++) { acc[i][0] = 0.0f; acc[i][1] = 0.0f; }

    for (int kc = 0; kc < KPART/32; kc++) {
        int k0 = kc * 32;
        const float* xsrc = (k0 < IN_DIM)
            ? (inp + (size_t)lrow*IN_DIM + k0 + lcol)
            : (h   + (size_t)lrow*H + (k0 - IN_DIM) + lcol);
        float4 xa = *(const float4*)xsrc;
        float4 xb = *(const float4*)(xsrc + 4);
        Xs[lrow][lcol+0]=xa.x; Xs[lrow][lcol+1]=xa.y; Xs[lrow][lcol+2]=xa.z; Xs[lrow][lcol+3]=xa.w;
        Xs[lrow][lcol+4]=xb.x; Xs[lrow][lcol+5]=xb.y; Xs[lrow][lcol+6]=xb.z; Xs[lrow][lcol+7]=xb.w;
        const float* wsrc = (k0 < IN_DIM)
            ? (W_ih + (size_t)(jbase + wrow)*(IN_DIM + M) + k0 + wcol)
            : (W_hh + (size_t)(jbase + wrow)*H + (k0 - IN_DIM) + wcol);
        float4 wa = *(const float4*)wsrc;
        Ws[wrow][wcol+0]=wa.x; Ws[wrow][wcol+1]=wa.y; Ws[wrow][wcol+2]=wa.z; Ws[wrow][wcol+3]=wa.w;
        __syncthreads();
        #pragma unroll
        for (int k = 0; k < 32; k++) {
            float xv[4], wv[2];
            #pragma unroll
            for (int i = 0; i < 4; i++) xv[i] = Xs[tx*4 + i][k];
            wv[0] = Ws[ty*2 + 0][k];
            wv[1] = Ws[ty*2 + 1][k];
            #pragma unroll
            for (int i = 0; i < 4; i++) {
                acc[i][0] += xv[i] * wv[0];
                acc[i][1] += xv[i] * wv[1];
            }
        }
        __syncthreads();
    }
    #pragma unroll
    for (int jj = 0; jj < 2; jj++) {
        int j = jbase + ty*2 + jj;
        float bias = b_ih[j] + b_hh[j];
        #pragma unroll
        for (int i = 0; i < 4; i++)
            g_gatesT[(size_t)j*B + (tx*4 + i)] = acc[i][jj] + bias;
    }
}

// ---------------------------------------------------------------------------
// Dot tile (128 rows): prefetch -> optional spin -> compute logits.
// ---------------------------------------------------------------------------
__device__ void dot_tile(const float* __restrict__ Mem, int b, int xt, int* flags)
{
    int t = threadIdx.x;
    int lane8 = t & 7, rowp = t >> 3;

    float4 pf[8];
    size_t base = ((size_t)b*N + xt*DTILE)*M;
    #pragma unroll
    for (int it = 0; it < 4; it++) {
        const float4* p = (const float4*)(Mem + base + (size_t)(it*32 + rowp)*M) + lane8*2;
        pf[it*2]   = p[0];
        pf[it*2+1] = p[1];
    }

    if (flags) spin_on(&flags[b]);

    int m0 = lane8 * 8;
    float4 ka = *(const float4*)(g_k + b*M + m0);
    float4 kb4 = *(const float4*)(g_k + b*M + m0 + 4);
    float beta = g_par[b*32 + 0];
    float nk   = g_par[b*32 + 6];

    #pragma unroll
    for (int it = 0; it < 4; it++) {
        float4 v0 = pf[it*2], v1 = pf[it*2+1];
        float d  = v0.x*ka.x + v0.y*ka.y + v0.z*ka.z + v0.w*ka.w
                 + v1.x*kb4.x + v1.y*kb4.y + v1.z*kb4.z + v1.w*kb4.w;
        float nm = v0.x*v0.x + v0.y*v0.y + v0.z*v0.z + v0.w*v0.w
                 + v1.x*v1.x + v1.y*v1.y + v1.z*v1.z + v1.w*v1.w;
        #pragma unroll
        for (int o = 4; o; o >>= 1) {
            d  += __shfl_xor_sync(0xffffffffu, d,  o);
            nm += __shfl_xor_sync(0xffffffffu, nm, o);
        }
        if (lane8 == 0) g_logit[(size_t)b*N + xt*DTILE + it*32 + rowp] = beta * d / (nm * nk);
    }
}

// ---------------------------------------------------------------------------
// Address (256 threads, one block per batch)
// ---------------------------------------------------------------------------
__device__ void address_dev(int b, const float* __restrict__ head_prev,
                            float* __restrict__ out_head)
{
    __shared__ float A[N];       // 32KB
    __shared__ float red[8];
    int t = threadIdx.x;
    float g     = g_par[b*32 + 1];
    float gamma = g_par[b*32 + 2];
    float s0    = g_par[b*32 + 3];
    float s1    = g_par[b*32 + 4];
    float s2    = g_par[b*32 + 5];

    const float* lg = g_logit + (size_t)b*N;
    float vmax = -FLT_MAX;
    #pragma unroll
    for (int i = 0; i < 32; i++) {
        float v = lg[i*256 + t];
        A[i*256 + t] = v;
        vmax = fmaxf(vmax, v);
    }
    vmax = bmax(vmax, red);

    float lsum = 0.0f;
    #pragma unroll
    for (int i = 0; i < 32; i++) {
        int idx = i*256 + t;
        float e = __expf(A[idx] - vmax);
        A[idx] = e;
        lsum += e;
    }
    float inv = 1.0f / bsum(lsum, red);

    const float* hp = head_prev + (size_t)b*N;
    #pragma unroll
    for (int i = 0; i < 32; i++) {
        int idx = i*256 + t;
        A[idx] = g * (A[idx] * inv) + (1.0f - g) * hp[idx];
    }
    __syncthreads();

    float p[32];
    float psum = 0.0f;
    #pragma unroll
    for (int i = 0; i < 32; i++) {
        int idx = i*256 + t;
        float o = s0 * A[(idx + N - 2) & (N-1)]
                + s1 * A[(idx + N - 1) & (N-1)]
                + s2 * A[idx];
        p[i] = __powf(o, gamma);
        psum += p[i];
    }
    float inv2 = 1.0f / bsum(psum, red);
    #pragma unroll
    for (int i = 0; i < 32; i++)
        out_head[(size_t)b*N + i*256 + t] = p[i] * inv2;
}

// ---------------------------------------------------------------------------
// M_read tile: prefetch -> spin fB -> weighted sum -> partial (no counters)
// ---------------------------------------------------------------------------
__device__ void mread_tile(const float* __restrict__ Mem,
                           const float* __restrict__ rhead, int b, int xt)
{
    int t = threadIdx.x;
    int lane8 = t & 7, rowp = t >> 3;

    float4 pf[8];
    size_t base = ((size_t)b*N + xt*DTILE)*M;
    #pragma unroll
    for (int it = 0; it < 4; it++) {
        const float4* p = (const float4*)(Mem + base + (size_t)(it*32 + rowp)*M) + lane8*2;
        pf[it*2]   = p[0];
        pf[it*2+1] = p[1];
    }

    spin_on(&fB[b]);

    float a0=0,a1=0,a2=0,a3=0,a4=0,a5=0,a6=0,a7=0;
    const float* hp = rhead + (size_t)b*N + xt*DTILE;
    #pragma unroll
    for (int it = 0; it < 4; it++) {
        float r = hp[it*32 + rowp];
        float4 v0 = pf[it*2], v1 = pf[it*2+1];
        a0 += r*v0.x; a1 += r*v0.y; a2 += r*v0.z; a3 += r*v0.w;
        a4 += r*v1.x; a5 += r*v1.y; a6 += r*v1.z; a7 += r*v1.w;
    }

    __shared__ float sdata[256*8];
    float* s = sdata + t*8;
    s[0]=a0; s[1]=a1; s[2]=a2; s[3]=a3; s[4]=a4; s[5]=a5; s[6]=a6; s[7]=a7;
    __syncthreads();
    if (t < 64) {
        int lg2 = t >> 3, j = t & 7;
        float acc = 0.0f;
        #pragma unroll
        for (int rw = 0; rw < 32; rw++) acc += sdata[((rw<<3) | lg2)*8 + j];
        g_mpart[((size_t)b*64 + xt)*M + lg2*8 + j] = acc;
    }
}

// ---------------------------------------------------------------------------
// fc: per-batch fused [partial-reduce -> gates fixup -> LSTM -> write ctrl].
// Needs: g_mpart(b) complete (prev launch), g_gatesT (P1), c.
// ---------------------------------------------------------------------------
__device__ void fc_dev(int b, const float* __restrict__ W_ih,
                       const float* __restrict__ c,
                       float* __restrict__ out_h, float* __restrict__ out_c,
                       const float* kw, const float* kb,
                       const float* cw, const float* cb,
                       const float* sw, const float* sb,
                       const float* ww, const float* wb)
{
    int t = threadIdx.x;
    __shared__ float mr[M];
    __shared__ float hs[H];
    __shared__ float sr[256];

    // reduce 64 partial chunks -> M_read[b]
    {
        int m = t & 63, q = t >> 6;
        float a = 0.0f;
        #pragma unroll
        for (int p = 0; p < 16; p++)
            a += g_mpart[((size_t)b*64 + q*16 + p)*M + m];
        sr[t] = a;
        __syncthreads();
        if (t < 64) mr[t] = sr[t] + sr[64+t] + sr[128+t] + sr[192+t];
        __syncthreads();
    }

    // gates fixup + LSTM cell: thread handles h = t and t+256
    #pragma unroll
    for (int i = 0; i < 2; i++) {
        int hh = t + i*256;
        float gv[4];
        #pragma unroll
        for (int gg = 0; gg < 4; gg++) {
            int j = gg*H + hh;
            float acc = g_gatesT[(size_t)j*B + b];
            const float4* w4 = (const float4*)(W_ih + (size_t)j*(IN_DIM + M) + IN_DIM);
            #pragma unroll
            for (int q = 0; q < 16; q++) {
                float4 wv = w4[q];
                acc += wv.x*mr[q*4+0] + wv.y*mr[q*4+1] + wv.z*mr[q*4+2] + wv.w*mr[q*4+3];
            }
            gv[gg] = acc;
        }
        float cn = sigf(gv[1]) * c[(size_t)b*H + hh] + sigf(gv[0]) * tanhf(gv[2]);
        float hn = sigf(gv[3]) * tanhf(cn);
        out_c[(size_t)b*H + hh] = cn;
        out_h[(size_t)b*H + hh] = hn;
        hs[hh] = hn;
    }
    __syncthreads();

    // write-controller on h_new (in smem)
    controller_core(b, hs, kw, kb, cw, cb, sw, sb, ww, wb);
}

// ---------------------------------------------------------------------------
// M_out tile: prefetch -> spin fD -> update (streaming stores)
// ---------------------------------------------------------------------------
__device__ void mout_tile(const float* __restrict__ Mem,
                          const float* __restrict__ whead,
                          float* __restrict__ outM, int b, int xt)
{
    int t = threadIdx.x;
    int lane8 = t & 7, rowp = t >> 3;

    float4 pf[8];
    size_t base = ((size_t)b*N + xt*DTILE)*M;
    #pragma unroll
    for (int it = 0; it < 4; it++) {
        const float4* p = (const float4*)(Mem + base + (size_t)(it*32 + rowp)*M) + lane8*2;
        pf[it*2]   = p[0];
        pf[it*2+1] = p[1];
    }

    spin_on(&fD[b]);

    int m0 = lane8 * 8;
    float4 e0v = *(const float4*)(g_ea + b*2*M + m0);
    float4 e1v = *(const float4*)(g_ea + b*2*M + m0 + 4);
    float4 a0v = *(const float4*)(g_ea + b*2*M + M + m0);
    float4 a1v = *(const float4*)(g_ea + b*2*M + M + m0 + 4);

    #pragma unroll
    for (int it = 0; it < 4; it++) {
        float w = whead[(size_t)b*N + xt*DTILE + it*32 + rowp];
        float4 v0 = pf[it*2], v1 = pf[it*2+1];
        float4 o0, o1;
        o0.x = v0.x*(1.0f - w*e0v.x) + w*a0v.x;
        o0.y = v0.y*(1.0f - w*e0v.y) + w*a0v.y;
        o0.z = v0.z*(1.0f - w*e0v.z) + w*a0v.z;
        o0.w = v0.w*(1.0f - w*e0v.w) + w*a0v.w;
        o1.x = v1.x*(1.0f - w*e1v.x) + w*a1v.x;
        o1.y = v1.y*(1.0f - w*e1v.y) + w*a1v.y;
        o1.z = v1.z*(1.0f - w*e1v.z) + w*a1v.z;
        o1.w = v1.w*(1.0f - w*e1v.w) + w*a1v.w;
        float4* q = (float4*)(outM + base + (size_t)(it*32 + rowp)*M) + lane8*2;
        __stcs(q,     o0);
        __stcs(q + 1, o1);
    }
}

// ===========================================================================
// P1: ctrl(all) [0,64) | gemm [64,128) | dotR(G0) [128,1152)
// ===========================================================================
__global__ void __launch_bounds__(256) p1_kernel(
    const float* __restrict__ Mem, const float* __restrict__ inp,
    const float* __restrict__ h,
    const float* __restrict__ W_ih, const float* __restrict__ b_ih,
    const float* __restrict__ W_hh, const float* __restrict__ b_hh,
    const float* __restrict__ rk_w, const float* __restrict__ rk_b,
    const float* __restrict__ rc_w, const float* __restrict__ rc_b,
    const float* __restrict__ rs_w, const float* __restrict__ rs_b)
{
    int bid = blockIdx.x;
    if (bid < B) {
        if (threadIdx.x == 0) fD[bid] = 0;   // reset prev-replay fD
        controller_load(bid, h, rk_w, rk_b, rc_w, rc_b, rs_w, rs_b, nullptr, nullptr);
        release(&fA[bid]);
        return;
    }
    if (bid < 2*B) {
        gemm_partial(bid - B, inp, h, W_ih, b_ih, W_hh, b_hh);
        return;
    }
    int idx = bid - 2*B;
    dot_tile(Mem, idx >> 6, idx & 63, fA);
}

// ===========================================================================
// P2: addrR(G0) [0,16) | dotR(G1) [16,1040) | mread(G0) [1040,2064)
// ===========================================================================
__global__ void __launch_bounds__(256) p2_kernel(
    const float* __restrict__ Mem,
    const float* __restrict__ rhead, float* __restrict__ out_r)
{
    int bid = blockIdx.x;
    if (bid < GB) {
        if (threadIdx.x < 4) fA[bid*4 + threadIdx.x] = 0;   // reset P1 flags
        address_dev(bid, rhead, out_r);
        release(&fB[bid]);
        return;
    }
    if (bid < GB + 1024) {
        int idx = bid - GB;
        dot_tile(Mem, GB + (idx >> 6), idx & 63, nullptr);
        return;
    }
    int idx = bid - (GB + 1024);
    mread_tile(Mem, out_r, idx >> 6, idx & 63);
}

// ===========================================================================
// P3: addrR(G1) [0,16) | fc(G0) [16,32) | dotR(G2) [32,1056) |
//     dotW(G0) [1056,2080) | mread(G1) [2080,3104)
// ===========================================================================
__global__ void __launch_bounds__(256) p3_kernel(
    const float* __restrict__ Mem,
    const float* __restrict__ rhead, float* __restrict__ out_r,
    const float* __restrict__ W_ih, const float* __restrict__ c,
    float* __restrict__ out_h, float* __restrict__ out_c,
    const float* __restrict__ wk_w, const float* __restrict__ wk_b,
    const float* __restrict__ wc_w, const float* __restrict__ wc_b,
    const float* __restrict__ ws_w, const float* __restrict__ ws_b,
    const float* __restrict__ w_w,  const float* __restrict__ w_b)
{
    int bid = blockIdx.x;
    if (bid < GB) {
        int b = GB + bid;
        address_dev(b, rhead, out_r);
        release(&fB[b]);
        return;
    }
    if (bid < 2*GB) {
        int b = bid - GB;
        fc_dev(b, W_ih, c, out_h, out_c, wk_w, wk_b, wc_w, wc_b, ws_w, ws_b, w_w, w_b);
        release(&fC[b]);
        return;
    }
    if (bid < 2*GB + 1024) {
        int idx = bid - 2*GB;
        dot_tile(Mem, 2*GB + (idx >> 6), idx & 63, nullptr);
        return;
    }
    if (bid < 2*GB + 2048) {
        int idx = bid - (2*GB + 1024);
        dot_tile(Mem, idx >> 6, idx & 63, fC);
        return;
    }
    int idx = bid - (2*GB + 2048);
    mread_tile(Mem, out_r, GB + (idx >> 6), idx & 63);
}

// ===========================================================================
// P4: addrW(G0) [0,16) | addrR(G2) [16,32) | fc(G1) [32,48) |
//     dotR(G3) [48,1072) | dotW(G1) [1072,2096) | mread(G2) [2096,3120) |
//     mout(G0) [3120,4144)
// ===========================================================================
__global__ void __launch_bounds__(256) p4_kernel(
    const float* __restrict__ Mem,
    const float* __restrict__ rhead, const float* __restrict__ whead,
    float* __restrict__ out_r, float* __restrict__ out_w, float* __restrict__ out_m,
    const float* __restrict__ W_ih, const float* __restrict__ c,
    float* __restrict__ out_h, float* __restrict__ out_c,
    const float* __restrict__ wk_w, const float* __restrict__ wk_b,
    const float* __restrict__ wc_w, const float* __restrict__ wc_b,
    const float* __restrict__ ws_w, const float* __restrict__ ws_b,
    const float* __restrict__ w_w,  const float* __restrict__ w_b)
{
    int bid = blockIdx.x;
    if (bid < GB) {
        int b = bid;
        address_dev(b, whead, out_w);
        release(&fD[b]);
        return;
    }
    if (bid < 2*GB) {
        int b = 2*GB + (bid - GB);
        address_dev(b, rhead, out_r);
        release(&fB[b]);
        return;
    }
    if (bid < 3*GB) {
        int b = GB + (bid - 2*GB);
        fc_dev(b, W_ih, c, out_h, out_c, wk_w, wk_b, wc_w, wc_b, ws_w, ws_b, w_w, w_b);
        release(&fC[b]);
        return;
    }
    if (bid < 3*GB + 1024) {
        int idx = bid - 3*GB;
        dot_tile(Mem, 3*GB + (idx >> 6), idx & 63, nullptr);
        return;
    }
    if (bid < 3*GB + 2048) {
        int idx = bid - (3*GB + 1024);
        dot_tile(Mem, GB + (idx >> 6), idx & 63, fC);
        return;
    }
    if (bid < 3*GB + 3072) {
        int idx = bid - (3*GB + 2048);
        mread_tile(Mem, out_r, 2*GB + (idx >> 6), idx & 63);
        return;
    }
    int idx = bid - (3*GB + 3072);
    mout_tile(Mem, out_w, out_m, idx >> 6, idx & 63);
}

// ===========================================================================
// P5: addrW(G1) [0,16) | addrR(G3) [16,32) | fc(G2) [32,48) |
//     dotW(G2) [48,1072) | mread(G3) [1072,2096) | mout(G1) [2096,3120)
// ===========================================================================
__global__ void __launch_bounds__(256) p5_kernel(
    const float* __restrict__ Mem,
    const float* __restrict__ rhead, const float* __restrict__ whead,
    float* __restrict__ out_r, float* __restrict__ out_w, float* __restrict__ out_m,
    const float* __restrict__ W_ih, const float* __restrict__ c,
    float* __restrict__ out_h, float* __restrict__ out_c,
    const float* __restrict__ wk_w, const float* __restrict__ wk_b,
    const float* __restrict__ wc_w, const float* __restrict__ wc_b,
    const float* __restrict__ ws_w, const float* __restrict__ ws_b,
    const float* __restrict__ w_w,  const float* __restrict__ w_b)
{
    int bid = blockIdx.x;
    if (bid < GB) {
        int b = GB + bid;
        address_dev(b, whead, out_w);
        release(&fD[b]);
        return;
    }
    if (bid < 2*GB) {
        int b = 3*GB + (bid - GB);
        address_dev(b, rhead, out_r);
        release(&fB[b]);
        return;
    }
    if (bid < 3*GB) {
        int b = 2*GB + (bid - 2*GB);
        fc_dev(b, W_ih, c, out_h, out_c, wk_w, wk_b, wc_w, wc_b, ws_w, ws_b, w_w, w_b);
        release(&fC[b]);
        return;
    }
    if (bid < 3*GB + 1024) {
        int idx = bid - 3*GB;
        dot_tile(Mem, 2*GB + (idx >> 6), idx & 63, fC);
        return;
    }
    if (bid < 3*GB + 2048) {
        int idx = bid - (3*GB + 1024);
        mread_tile(Mem, out_r, 3*GB + (idx >> 6), idx & 63);
        return;
    }
    int idx = bid - (3*GB + 2048);
    mout_tile(Mem, out_w, out_m, GB + (idx >> 6), idx & 63);
}

// ===========================================================================
// P6: addrW(G2) [0,16) | fc(G3) [16,32) | dotW(G3) [32,1056) | mout(G2) [1056,2080)
// ===========================================================================
__global__ void __launch_bounds__(256) p6_kernel(
    const float* __restrict__ Mem, const float* __restrict__ whead,
    float* __restrict__ out_w, float* __restrict__ out_m,
    const float* __restrict__ W_ih, const float* __restrict__ c,
    float* __restrict__ out_h, float* __restrict__ out_c,
    const float* __restrict__ wk_w, const float* __restrict__ wk_b,
    const float* __restrict__ wc_w, const float* __restrict__ wc_b,
    const float* __restrict__ ws_w, const float* __restrict__ ws_b,
    const float* __restrict__ w_w,  const float* __restrict__ w_b)
{
    int bid = blockIdx.x;
    if (bid < GB) {
        int b = 2*GB + bid;
        address_dev(b, whead, out_w);
        release(&fD[b]);
        return;
    }
    if (bid < 2*GB) {
        int b = 3*GB + (bid - GB);
        fc_dev(b, W_ih, c, out_h, out_c, wk_w, wk_b, wc_w, wc_b, ws_w, ws_b, w_w, w_b);
        release(&fC[b]);
        return;
    }
    if (bid < 2*GB + 1024) {
        int idx = bid - 2*GB;
        dot_tile(Mem, 3*GB + (idx >> 6), idx & 63, fC);
        return;
    }
    int idx = bid - (2*GB + 1024);
    mout_tile(Mem, out_w, out_m, 2*GB + (idx >> 6), idx & 63);
}

// ===========================================================================
// P7: addrW(G3) [0,16) | mout(G3) [16,1040)    (+ reset fB/fC)
// ===========================================================================
__global__ void __launch_bounds__(256) p7_kernel(
    const float* __restrict__ Mem, const float* __restrict__ whead,
    float* __restrict__ out_w, float* __restrict__ out_m)
{
    int bid = blockIdx.x;
    if (bid < GB) {
        int b = 3*GB + bid;
        if (threadIdx.x < 4) {
            fB[bid*4 + threadIdx.x] = 0;
            fC[bid*4 + threadIdx.x] = 0;
        }
        address_dev(b, whead, out_w);
        release(&fD[b]);
        return;
    }
    int idx = bid - GB;
    mout_tile(Mem, out_w, out_m, 3*GB + (idx >> 6), idx & 63);
}

// ---------------------------------------------------------------------------
extern "C" void kernel_launch(void* const* d_in, const int* in_sizes, int n_in,
                              void* d_out, int out_size)
{
    const float* inp    = (const float*)d_in[0];
    const float* h      = (const float*)d_in[1];
    const float* c      = (const float*)d_in[2];
    const float* rhead  = (const float*)d_in[3];
    const float* whead  = (const float*)d_in[4];
    const float* mem    = (const float*)d_in[5];
    const float* W_ih   = (const float*)d_in[6];
    const float* b_ih   = (const float*)d_in[7];
    const float* W_hh   = (const float*)d_in[8];
    const float* b_hh   = (const float*)d_in[9];
    const float* rk_w   = (const float*)d_in[10];
    const float* rk_b   = (const float*)d_in[11];
    const float* rc_w   = (const float*)d_in[12];
    const float* rc_b   = (const float*)d_in[13];
    const float* rs_w   = (const float*)d_in[14];
    const float* rs_b   = (const float*)d_in[15];
    const float* wk_w   = (const float*)d_in[16];
    const float* wk_b   = (const float*)d_in[17];
    const float* wc_w   = (const float*)d_in[18];
    const float* wc_b   = (const float*)d_in[19];
    const float* ws_w   = (const float*)d_in[20];
    const float* ws_b   = (const float*)d_in[21];
    const float* w_w    = (const float*)d_in[22];
    const float* w_b    = (const float*)d_in[23];

    float* out   = (float*)d_out;
    float* out_h = out;
    float* out_c = out + OUT_C_OFF;
    float* out_r = out + OUT_R_OFF;
    float* out_w = out + OUT_W_OFF;
    float* out_m = out + OUT_M_OFF;

    p1_kernel<<<2*B + 1024, 256>>>(mem, inp, h, W_ih, b_ih, W_hh, b_hh,
                                   rk_w, rk_b, rc_w, rc_b, rs_w, rs_b);
    p2_kernel<<<GB + 2048, 256>>>(mem, rhead, out_r);
    p3_kernel<<<2*GB + 3072, 256>>>(mem, rhead, out_r, W_ih, c, out_h, out_c,
                                    wk_w, wk_b, wc_w, wc_b, ws_w, ws_b, w_w, w_b);
    p4_kernel<<<3*GB + 4096, 256>>>(mem, rhead, whead, out_r, out_w, out_m,
                                    W_ih, c, out_h, out_c,
                                    wk_w, wk_b, wc_w, wc_b, ws_w, ws_b, w_w, w_b);
    p5_kernel<<<3*GB + 3072, 256>>>(mem, rhead, whead, out_r, out_w, out_m,
                                    W_ih, c, out_h, out_c,
                                    wk_w, wk_b, wc_w, wc_b, ws_w, ws_b, w_w, w_b);
    p6_kernel<<<2*GB + 2048, 256>>>(mem, whead, out_w, out_m,
                                    W_ih, c, out_h, out_c,
                                    wk_w, wk_b, wc_w, wc_b, ws_w, ws_b, w_w, w_b);
    p7_kernel<<<GB + 1024, 256>>>(mem, whead, out_w, out_m);
}

// round 10
// speedup vs baseline: 1.7342x; 1.7342x over previous
#include <cuda_runtime.h>
#include <cuda_bf16.h>
#include <float.h>
#include <math.h>

// Problem constants
#define B 64
#define IN_DIM 256
#define H 512
#define M 64
#define N 8192
#define GJ 2048          // 4*H
#define KPART 768        // inp + h K-columns
#define DTILE 128        // rows per Mem tile (64 tiles per batch)

// Output layout (floats)
#define OUT_C_OFF (B*H)
#define OUT_R_OFF (2*B*H)
#define OUT_W_OFF (2*B*H + B*N)
#define OUT_M_OFF (2*B*H + 2*B*N)

// Scratch (static device globals — no allocation)
__device__ float g_k[B*M];
__device__ __align__(128) float g_par[B*32];
__device__ float g_logit[B*N];
__device__ float g_mpart[B*64*M];
__device__ float g_gatesT[GJ*B];              // partial gates [j][b]
__device__ float g_ea[B*2*M];

// Flags (zero-init). Lifecycle: set+used in one launch, reset one launch later.
//  fA: set+used K1 -> reset K2 (addr blocks)
//  fB: set+used K2 -> reset K3 (fc blocks)
//  fC: set+used K3 -> reset K4 (addr blocks)
//  fD: set+used K4 -> reset K1 (ctrl blocks, next replay)
__device__ int fA[B];
__device__ int fB[B];
__device__ int fC[B];
__device__ int fD[B];

__device__ __forceinline__ float sigf(float x) { return 1.0f / (1.0f + __expf(-x)); }

__device__ __forceinline__ void spin_on(int* f)
{
    if (threadIdx.x == 0) {
        while (atomicAdd(f, 0) == 0) __nanosleep(64);
    }
    __syncthreads();
    __threadfence();
}

__device__ __forceinline__ void release(int* f)
{
    __threadfence();
    __syncthreads();
    if (threadIdx.x == 0) atomicExch(f, 1);
}

// ---------------------------------------------------------------------------
// Block reductions (256 threads, 8 warps)
// ---------------------------------------------------------------------------
__device__ __forceinline__ float bsum(float v, float* red)
{
    #pragma unroll
    for (int o = 16; o; o >>= 1) v += __shfl_xor_sync(0xffffffffu, v, o);
    int t = threadIdx.x;
    if ((t & 31) == 0) red[t >> 5] = v;
    __syncthreads();
    if (t < 8) {
        v = red[t];
        #pragma unroll
        for (int o = 4; o; o >>= 1) v += __shfl_xor_sync(0xffu, v, o);
        if (t == 0) red[0] = v;
    }
    __syncthreads();
    float r = red[0];
    __syncthreads();
    return r;
}

__device__ __forceinline__ float bmax(float v, float* red)
{
    #pragma unroll
    for (int o = 16; o; o >>= 1) v = fmaxf(v, __shfl_xor_sync(0xffffffffu, v, o));
    int t = threadIdx.x;
    if ((t & 31) == 0) red[t >> 5] = v;
    __syncthreads();
    if (t < 8) {
        v = red[t];
        #pragma unroll
        for (int o = 4; o; o >>= 1) v = fmaxf(v, __shfl_xor_sync(0xffu, v, o));
        if (t == 0) red[0] = v;
    }
    __syncthreads();
    float r = red[0];
    __syncthreads();
    return r;
}

// ---------------------------------------------------------------------------
// Controller core: hs (h state) already in shared memory.
// ---------------------------------------------------------------------------
__device__ void controller_core(int b, const float* hs,
                                const float* __restrict__ kw, const float* __restrict__ kb,
                                const float* __restrict__ cw, const float* __restrict__ cb,
                                const float* __restrict__ sw, const float* __restrict__ sb,
                                const float* __restrict__ ww, const float* __restrict__ wb)
{
    int t = threadIdx.x;
    __shared__ float ks[M];
    __shared__ float cvs[3];
    __shared__ float ss[3];

    if (t < M) {
        const float4* w4 = (const float4*)(kw + (size_t)t * H);
        float acc = kb[t];
        #pragma unroll 8
        for (int q = 0; q < H/4; q++) {
            float4 wv = w4[q]; int j = q*4;
            acc += wv.x*hs[j] + wv.y*hs[j+1] + wv.z*hs[j+2] + wv.w*hs[j+3];
        }
        ks[t] = tanhf(acc);
    } else if (t < M + 3) {
        int r = t - M;
        const float4* w4 = (const float4*)(cw + (size_t)r * H);
        float acc = cb[r];
        for (int q = 0; q < H/4; q++) {
            float4 wv = w4[q]; int j = q*4;
            acc += wv.x*hs[j] + wv.y*hs[j+1] + wv.z*hs[j+2] + wv.w*hs[j+3];
        }
        cvs[r] = acc;
    } else if (t < M + 6) {
        int r = t - M - 3;
        const float4* w4 = (const float4*)(sw + (size_t)r * H);
        float acc = sb[r];
        for (int q = 0; q < H/4; q++) {
            float4 wv = w4[q]; int j = q*4;
            acc += wv.x*hs[j] + wv.y*hs[j+1] + wv.z*hs[j+2] + wv.w*hs[j+3];
        }
        ss[r] = acc;
    } else if (ww != nullptr && t >= 70 && t < 70 + 2*M) {
        int r = t - 70;
        const float4* w4 = (const float4*)(ww + (size_t)r * H);
        float acc = wb[r];
        for (int q = 0; q < H/4; q++) {
            float4 wv = w4[q]; int j = q*4;
            acc += wv.x*hs[j] + wv.y*hs[j+1] + wv.z*hs[j+2] + wv.w*hs[j+3];
        }
        g_ea[b*2*M + r] = (r < M) ? sigf(acc) : acc;
    }
    __syncthreads();

    if (t < M) g_k[b*M + t] = ks[t];
    if (t == 0) {
        float mx = fmaxf(ss[0], fmaxf(ss[1], ss[2]));
        float e0 = __expf(ss[0]-mx), e1 = __expf(ss[1]-mx), e2 = __expf(ss[2]-mx);
        float tot = e0 + e1 + e2;
        float nk = 0.0f;
        for (int j = 0; j < M; j++) nk += ks[j]*ks[j];
        g_par[b*32 + 0] = fmaxf(cvs[0], 0.0f) + 0.0001f;
        g_par[b*32 + 1] = sigf(cvs[1]);
        g_par[b*32 + 2] = fmaxf(cvs[2], 0.0f) + 1.0001f;
        g_par[b*32 + 3] = e0/tot;
        g_par[b*32 + 4] = e1/tot;
        g_par[b*32 + 5] = e2/tot;
        g_par[b*32 + 6] = nk;
    }
}

__device__ void controller_load(int b, const float* __restrict__ hstate,
                                const float* kw, const float* kb,
                                const float* cw, const float* cb,
                                const float* sw, const float* sb,
                                const float* ww, const float* wb)
{
    __shared__ float hs[H];
    int t = threadIdx.x;
    for (int i = t; i < H; i += 256) hs[i] = hstate[(size_t)b*H + i];
    __syncthreads();
    controller_core(b, hs, kw, kb, cw, cb, sw, sb, ww, wb);
}

// ---------------------------------------------------------------------------
// GEMM-partial: gatesT[j][b] = bias_j + inp[b]@W_ih[j,:256] + h[b]@W_hh[j,:]
// ---------------------------------------------------------------------------
__device__ void gemm_partial(int gbid,
                             const float* __restrict__ inp,
                             const float* __restrict__ h,
                             const float* __restrict__ W_ih,
                             const float* __restrict__ b_ih,
                             const float* __restrict__ W_hh,
                             const float* __restrict__ b_hh)
{
    __shared__ float Xs[64][33];
    __shared__ float Ws[32][33];
    int t  = threadIdx.x;
    int tx = t & 15;
    int ty = t >> 4;
    int jbase = gbid * 32;
    int lrow = t >> 2;
    int lcol = (t & 3) * 8;
    int wrow = t >> 3;
    int wcol = (t & 7) * 4;

    float acc[4][2];
    #pragma unroll
    for (int i = 0; i < 4; i++) { acc[i][0] = 0.0f; acc[i][1] = 0.0f; }

    for (int kc = 0; kc < KPART/32; kc++) {
        int k0 = kc * 32;
        const float* xsrc = (k0 < IN_DIM)
            ? (inp + (size_t)lrow*IN_DIM + k0 + lcol)
            : (h   + (size_t)lrow*H + (k0 - IN_DIM) + lcol);
        float4 xa = *(const float4*)xsrc;
        float4 xb = *(const float4*)(xsrc + 4);
        Xs[lrow][lcol+0]=xa.x; Xs[lrow][lcol+1]=xa.y; Xs[lrow][lcol+2]=xa.z; Xs[lrow][lcol+3]=xa.w;
        Xs[lrow][lcol+4]=xb.x; Xs[lrow][lcol+5]=xb.y; Xs[lrow][lcol+6]=xb.z; Xs[lrow][lcol+7]=xb.w;
        const float* wsrc = (k0 < IN_DIM)
            ? (W_ih + (size_t)(jbase + wrow)*(IN_DIM + M) + k0 + wcol)
            : (W_hh + (size_t)(jbase + wrow)*H + (k0 - IN_DIM) + wcol);
        float4 wa = *(const float4*)wsrc;
        Ws[wrow][wcol+0]=wa.x; Ws[wrow][wcol+1]=wa.y; Ws[wrow][wcol+2]=wa.z; Ws[wrow][wcol+3]=wa.w;
        __syncthreads();
        #pragma unroll
        for (int k = 0; k < 32; k++) {
            float xv[4], wv[2];
            #pragma unroll
            for (int i = 0; i < 4; i++) xv[i] = Xs[tx*4 + i][k];
            wv[0] = Ws[ty*2 + 0][k];
            wv[1] = Ws[ty*2 + 1][k];
            #pragma unroll
            for (int i = 0; i < 4; i++) {
                acc[i][0] += xv[i] * wv[0];
                acc[i][1] += xv[i] * wv[1];
            }
        }
        __syncthreads();
    }
    #pragma unroll
    for (int jj = 0; jj < 2; jj++) {
        int j = jbase + ty*2 + jj;
        float bias = b_ih[j] + b_hh[j];
        #pragma unroll
        for (int i = 0; i < 4; i++)
            g_gatesT[(size_t)j*B + (tx*4 + i)] = acc[i][jj] + bias;
    }
}

// ---------------------------------------------------------------------------
// Dot tile (128 rows): prefetch -> spin -> compute logits.
// ---------------------------------------------------------------------------
__device__ void dot_tile(const float* __restrict__ Mem, int b, int xt, int* flags)
{
    int t = threadIdx.x;
    int lane8 = t & 7, rowp = t >> 3;

    float4 pf[8];
    size_t base = ((size_t)b*N + xt*DTILE)*M;
    #pragma unroll
    for (int it = 0; it < 4; it++) {
        const float4* p = (const float4*)(Mem + base + (size_t)(it*32 + rowp)*M) + lane8*2;
        pf[it*2]   = p[0];
        pf[it*2+1] = p[1];
    }

    spin_on(&flags[b]);

    int m0 = lane8 * 8;
    float4 ka = *(const float4*)(g_k + b*M + m0);
    float4 kb4 = *(const float4*)(g_k + b*M + m0 + 4);
    float beta = g_par[b*32 + 0];
    float nk   = g_par[b*32 + 6];

    #pragma unroll
    for (int it = 0; it < 4; it++) {
        float4 v0 = pf[it*2], v1 = pf[it*2+1];
        float d  = v0.x*ka.x + v0.y*ka.y + v0.z*ka.z + v0.w*ka.w
                 + v1.x*kb4.x + v1.y*kb4.y + v1.z*kb4.z + v1.w*kb4.w;
        float nm = v0.x*v0.x + v0.y*v0.y + v0.z*v0.z + v0.w*v0.w
                 + v1.x*v1.x + v1.y*v1.y + v1.z*v1.z + v1.w*v1.w;
        #pragma unroll
        for (int o = 4; o; o >>= 1) {
            d  += __shfl_xor_sync(0xffffffffu, d,  o);
            nm += __shfl_xor_sync(0xffffffffu, nm, o);
        }
        if (lane8 == 0) g_logit[(size_t)b*N + xt*DTILE + it*32 + rowp] = beta * d / (nm * nk);
    }
}

// ---------------------------------------------------------------------------
// Address (256 threads, one block per batch)
// ---------------------------------------------------------------------------
__device__ void address_dev(int b, const float* __restrict__ head_prev,
                            float* __restrict__ out_head)
{
    __shared__ float A[N];       // 32KB
    __shared__ float red[8];
    int t = threadIdx.x;
    float g     = g_par[b*32 + 1];
    float gamma = g_par[b*32 + 2];
    float s0    = g_par[b*32 + 3];
    float s1    = g_par[b*32 + 4];
    float s2    = g_par[b*32 + 5];

    const float* lg = g_logit + (size_t)b*N;
    float vmax = -FLT_MAX;
    #pragma unroll
    for (int i = 0; i < 32; i++) {
        float v = lg[i*256 + t];
        A[i*256 + t] = v;
        vmax = fmaxf(vmax, v);
    }
    vmax = bmax(vmax, red);

    float lsum = 0.0f;
    #pragma unroll
    for (int i = 0; i < 32; i++) {
        int idx = i*256 + t;
        float e = __expf(A[idx] - vmax);
        A[idx] = e;
        lsum += e;
    }
    float inv = 1.0f / bsum(lsum, red);

    const float* hp = head_prev + (size_t)b*N;
    #pragma unroll
    for (int i = 0; i < 32; i++) {
        int idx = i*256 + t;
        A[idx] = g * (A[idx] * inv) + (1.0f - g) * hp[idx];
    }
    __syncthreads();

    float p[32];
    float psum = 0.0f;
    #pragma unroll
    for (int i = 0; i < 32; i++) {
        int idx = i*256 + t;
        float o = s0 * A[(idx + N - 2) & (N-1)]
                + s1 * A[(idx + N - 1) & (N-1)]
                + s2 * A[idx];
        p[i] = __powf(o, gamma);
        psum += p[i];
    }
    float inv2 = 1.0f / bsum(psum, red);
    #pragma unroll
    for (int i = 0; i < 32; i++)
        out_head[(size_t)b*N + i*256 + t] = p[i] * inv2;
}

// ---------------------------------------------------------------------------
// M_read tile: prefetch -> spin fB -> weighted sum -> write partial.
// (No counters; fc in the next launch reduces the partials.)
// ---------------------------------------------------------------------------
__device__ void mread_tile(const float* __restrict__ Mem,
                           const float* __restrict__ rhead, int b, int xt)
{
    int t = threadIdx.x;
    int lane8 = t & 7, rowp = t >> 3;

    float4 pf[8];
    size_t base = ((size_t)b*N + xt*DTILE)*M;
    #pragma unroll
    for (int it = 0; it < 4; it++) {
        const float4* p = (const float4*)(Mem + base + (size_t)(it*32 + rowp)*M) + lane8*2;
        pf[it*2]   = p[0];
        pf[it*2+1] = p[1];
    }

    spin_on(&fB[b]);

    float a0=0,a1=0,a2=0,a3=0,a4=0,a5=0,a6=0,a7=0;
    const float* hp = rhead + (size_t)b*N + xt*DTILE;
    #pragma unroll
    for (int it = 0; it < 4; it++) {
        float r = hp[it*32 + rowp];
        float4 v0 = pf[it*2], v1 = pf[it*2+1];
        a0 += r*v0.x; a1 += r*v0.y; a2 += r*v0.z; a3 += r*v0.w;
        a4 += r*v1.x; a5 += r*v1.y; a6 += r*v1.z; a7 += r*v1.w;
    }

    __shared__ float sdata[256*8];
    float* s = sdata + t*8;
    s[0]=a0; s[1]=a1; s[2]=a2; s[3]=a3; s[4]=a4; s[5]=a5; s[6]=a6; s[7]=a7;
    __syncthreads();
    if (t < 64) {
        int lg2 = t >> 3, j = t & 7;
        float acc = 0.0f;
        #pragma unroll
        for (int rw = 0; rw < 32; rw++) acc += sdata[((rw<<3) | lg2)*8 + j];
        g_mpart[((size_t)b*64 + xt)*M + lg2*8 + j] = acc;
    }
}

// ---------------------------------------------------------------------------
// fc: per-batch fused [partial-reduce -> gates fixup -> LSTM -> write ctrl].
// Reads only prev-launch data (g_mpart, g_gatesT, c) — no intra-launch deps.
// ---------------------------------------------------------------------------
__device__ void fc_dev(int b, const float* __restrict__ W_ih,
                       const float* __restrict__ c,
                       float* __restrict__ out_h, float* __restrict__ out_c,
                       const float* kw, const float* kb,
                       const float* cw, const float* cb,
                       const float* sw, const float* sb,
                       const float* ww, const float* wb)
{
    int t = threadIdx.x;
    __shared__ float mr[M];
    __shared__ float hs[H];
    __shared__ float sr[256];

    // reduce 64 partial chunks -> M_read[b]
    {
        int m = t & 63, q = t >> 6;
        float a = 0.0f;
        #pragma unroll
        for (int p = 0; p < 16; p++)
            a += g_mpart[((size_t)b*64 + q*16 + p)*M + m];
        sr[t] = a;
        __syncthreads();
        if (t < 64) mr[t] = sr[t] + sr[64+t] + sr[128+t] + sr[192+t];
        __syncthreads();
    }

    // gates fixup + LSTM cell: thread handles h = t and t+256
    #pragma unroll
    for (int i = 0; i < 2; i++) {
        int hh = t + i*256;
        float gv[4];
        #pragma unroll
        for (int gg = 0; gg < 4; gg++) {
            int j = gg*H + hh;
            float acc = g_gatesT[(size_t)j*B + b];
            const float4* w4 = (const float4*)(W_ih + (size_t)j*(IN_DIM + M) + IN_DIM);
            #pragma unroll
            for (int q = 0; q < 16; q++) {
                float4 wv = w4[q];
                acc += wv.x*mr[q*4+0] + wv.y*mr[q*4+1] + wv.z*mr[q*4+2] + wv.w*mr[q*4+3];
            }
            gv[gg] = acc;
        }
        float cn = sigf(gv[1]) * c[(size_t)b*H + hh] + sigf(gv[0]) * tanhf(gv[2]);
        float hn = sigf(gv[3]) * tanhf(cn);
        out_c[(size_t)b*H + hh] = cn;
        out_h[(size_t)b*H + hh] = hn;
        hs[hh] = hn;
    }
    __syncthreads();

    // write-controller on h_new (in smem)
    controller_core(b, hs, kw, kb, cw, cb, sw, sb, ww, wb);
}

// ---------------------------------------------------------------------------
// M_out tile: prefetch -> spin fD -> update (streaming stores)
// ---------------------------------------------------------------------------
__device__ void mout_tile(const float* __restrict__ Mem,
                          const float* __restrict__ whead,
                          float* __restrict__ outM, int b, int xt)
{
    int t = threadIdx.x;
    int lane8 = t & 7, rowp = t >> 3;

    float4 pf[8];
    size_t base = ((size_t)b*N + xt*DTILE)*M;
    #pragma unroll
    for (int it = 0; it < 4; it++) {
        const float4* p = (const float4*)(Mem + base + (size_t)(it*32 + rowp)*M) + lane8*2;
        pf[it*2]   = p[0];
        pf[it*2+1] = p[1];
    }

    spin_on(&fD[b]);

    int m0 = lane8 * 8;
    float4 e0v = *(const float4*)(g_ea + b*2*M + m0);
    float4 e1v = *(const float4*)(g_ea + b*2*M + m0 + 4);
    float4 a0v = *(const float4*)(g_ea + b*2*M + M + m0);
    float4 a1v = *(const float4*)(g_ea + b*2*M + M + m0 + 4);

    #pragma unroll
    for (int it = 0; it < 4; it++) {
        float w = whead[(size_t)b*N + xt*DTILE + it*32 + rowp];
        float4 v0 = pf[it*2], v1 = pf[it*2+1];
        float4 o0, o1;
        o0.x = v0.x*(1.0f - w*e0v.x) + w*a0v.x;
        o0.y = v0.y*(1.0f - w*e0v.y) + w*a0v.y;
        o0.z = v0.z*(1.0f - w*e0v.z) + w*a0v.z;
        o0.w = v0.w*(1.0f - w*e0v.w) + w*a0v.w;
        o1.x = v1.x*(1.0f - w*e1v.x) + w*a1v.x;
        o1.y = v1.y*(1.0f - w*e1v.y) + w*a1v.y;
        o1.z = v1.z*(1.0f - w*e1v.z) + w*a1v.z;
        o1.w = v1.w*(1.0f - w*e1v.w) + w*a1v.w;
        float4* q = (float4*)(outM + base + (size_t)(it*32 + rowp)*M) + lane8*2;
        __stcs(q,     o0);
        __stcs(q + 1, o1);
    }
}

// ===========================================================================
// K1: ctrl(read) [0,64) | gemm [64,128) | dotR FWD [128, 128+4096)
// ===========================================================================
__global__ void __launch_bounds__(256) k1_kernel(
    const float* __restrict__ Mem, const float* __restrict__ inp,
    const float* __restrict__ h,
    const float* __restrict__ W_ih, const float* __restrict__ b_ih,
    const float* __restrict__ W_hh, const float* __restrict__ b_hh,
    const float* __restrict__ rk_w, const float* __restrict__ rk_b,
    const float* __restrict__ rc_w, const float* __restrict__ rc_b,
    const float* __restrict__ rs_w, const float* __restrict__ rs_b)
{
    int bid = blockIdx.x;
    if (bid < B) {
        if (threadIdx.x == 0) fD[bid] = 0;   // reset K4 flags (prev replay)
        controller_load(bid, h, rk_w, rk_b, rc_w, rc_b, rs_w, rs_b, nullptr, nullptr);
        release(&fA[bid]);
        return;
    }
    if (bid < 2*B) {
        gemm_partial(bid - B, inp, h, W_ih, b_ih, W_hh, b_hh);
        return;
    }
    int idx = bid - 2*B;
    dot_tile(Mem, idx >> 6, idx & 63, fA);          // forward
}

// ===========================================================================
// K2: addrR [0,64) | mread REV [64, 64+4096)
// ===========================================================================
__global__ void __launch_bounds__(256) k2_kernel(
    const float* __restrict__ Mem,
    const float* __restrict__ rhead, float* __restrict__ out_r)
{
    int bid = blockIdx.x;
    if (bid < B) {
        if (threadIdx.x == 0) fA[bid] = 0;   // reset K1 flags
        address_dev(bid, rhead, out_r);
        release(&fB[bid]);
        return;
    }
    int idx = bid - B;
    int b  = B - 1 - (idx >> 6);             // reversed (serpentine after K1 fwd)
    int xt = 63 - (idx & 63);
    mread_tile(Mem, out_r, b, xt);
}

// ===========================================================================
// K3: fc [0,64) | dotW FWD [64, 64+4096)
// ===========================================================================
__global__ void __launch_bounds__(256) k3_kernel(
    const float* __restrict__ Mem,
    const float* __restrict__ W_ih, const float* __restrict__ c,
    float* __restrict__ out_h, float* __restrict__ out_c,
    const float* __restrict__ wk_w, const float* __restrict__ wk_b,
    const float* __restrict__ wc_w, const float* __restrict__ wc_b,
    const float* __restrict__ ws_w, const float* __restrict__ ws_b,
    const float* __restrict__ w_w,  const float* __restrict__ w_b)
{
    int bid = blockIdx.x;
    if (bid < B) {
        if (threadIdx.x == 0) fB[bid] = 0;   // reset K2 flags
        fc_dev(bid, W_ih, c, out_h, out_c,
               wk_w, wk_b, wc_w, wc_b, ws_w, ws_b, w_w, w_b);
        release(&fC[bid]);
        return;
    }
    int idx = bid - B;
    dot_tile(Mem, idx >> 6, idx & 63, fC);   // forward (serpentine after K2 rev)
}

// ===========================================================================
// K4: addrW [0,64) | mout REV [64, 64+4096)
// ===========================================================================
__global__ void __launch_bounds__(256) k4_kernel(
    const float* __restrict__ Mem, const float* __restrict__ whead,
    float* __restrict__ out_w, float* __restrict__ out_m)
{
    int bid = blockIdx.x;
    if (bid < B) {
        if (threadIdx.x == 0) fC[bid] = 0;   // reset K3 flags
        address_dev(bid, whead, out_w);
        release(&fD[bid]);
        return;
    }
    int idx = bid - B;
    int b  = B - 1 - (idx >> 6);             // reversed (serpentine after K3 fwd)
    int xt = 63 - (idx & 63);
    mout_tile(Mem, out_w, out_m, b, xt);
}

// ---------------------------------------------------------------------------
extern "C" void kernel_launch(void* const* d_in, const int* in_sizes, int n_in,
                              void* d_out, int out_size)
{
    const float* inp    = (const float*)d_in[0];
    const float* h      = (const float*)d_in[1];
    const float* c      = (const float*)d_in[2];
    const float* rhead  = (const float*)d_in[3];
    const float* whead  = (const float*)d_in[4];
    const float* mem    = (const float*)d_in[5];
    const float* W_ih   = (const float*)d_in[6];
    const float* b_ih   = (const float*)d_in[7];
    const float* W_hh   = (const float*)d_in[8];
    const float* b_hh   = (const float*)d_in[9];
    const float* rk_w   = (const float*)d_in[10];
    const float* rk_b   = (const float*)d_in[11];
    const float* rc_w   = (const float*)d_in[12];
    const float* rc_b   = (const float*)d_in[13];
    const float* rs_w   = (const float*)d_in[14];
    const float* rs_b   = (const float*)d_in[15];
    const float* wk_w   = (const float*)d_in[16];
    const float* wk_b   = (const float*)d_in[17];
    const float* wc_w   = (const float*)d_in[18];
    const float* wc_b   = (const float*)d_in[19];
    const float* ws_w   = (const float*)d_in[20];
    const float* ws_b   = (const float*)d_in[21];
    const float* w_w    = (const float*)d_in[22];
    const float* w_b    = (const float*)d_in[23];

    float* out   = (float*)d_out;
    float* out_h = out;
    float* out_c = out + OUT_C_OFF;
    float* out_r = out + OUT_R_OFF;
    float* out_w = out + OUT_W_OFF;
    float* out_m = out + OUT_M_OFF;

    k1_kernel<<<2*B + 4096, 256>>>(mem, inp, h, W_ih, b_ih, W_hh, b_hh,
                                   rk_w, rk_b, rc_w, rc_b, rs_w, rs_b);
    k2_kernel<<<B + 4096, 256>>>(mem, rhead, out_r);
    k3_kernel<<<B + 4096, 256>>>(mem, W_ih, c, out_h, out_c,
                                 wk_w, wk_b, wc_w, wc_b, ws_w, ws_b,
                                 w_w, w_b);
    k4_kernel<<<B + 4096, 256>>>(mem, whead, out_w, out_m);
}